// round 17
// baseline (speedup 1.0000x reference)
#include <cuda_runtime.h>
#include <cuda_bf16.h>
#include <cstdint>

#define SEQ 4096
#define TGT 1024
#define SENC 3072
#define HID 1024
#define H3 3072
#define IN_DIM 544
#define VOC 50000
#define GINF 0xFF800000u   // -inf sentinel: real h values are always finite (|h|<1)

// ---------------- scratch (static device memory; no allocations) -------------
__device__ float g_x[SEQ * IN_DIM];            // embeddings concat  [4096,544]
__device__ float g_gi_enc[SENC * H3];          // encoder input gates
__device__ float g_gi_dec[TGT * H3];           // decoder input gates
__device__ float g_henc[(SENC + 1) * HID];     // row0 = h0 = 0, rows 1.. = states
__device__ float g_hdec[(TGT + 1) * HID];
__device__ float g_attn[TGT * SENC];           // energies -> attn weights (in place)
__device__ float g_cat[TGT * 2 * HID];         // [hidden_state | context]

// ---------------- poison h buffers (row0 = 0, rows 1..steps = -inf) ----------
__global__ void k_poison(uint4* p, int nvec) {
    const uint4 z = make_uint4(0u, 0u, 0u, 0u);
    const uint4 f = make_uint4(GINF, GINF, GINF, GINF);
    for (int i = blockIdx.x * blockDim.x + threadIdx.x; i < nvec;
         i += gridDim.x * blockDim.x)
        p[i] = (i < HID / 4) ? z : f;
}

// ---------------- embed ------------------------------------------------------
__global__ void k_embed(const int* __restrict__ loc, const int* __restrict__ tim,
                        const float* __restrict__ el, const float* __restrict__ et,
                        float* __restrict__ x) {
    int i = blockIdx.x;
    int t = threadIdx.x;                       // 128 threads
    float4* dst = (float4*)(x + (size_t)i * IN_DIM);
    const float4* sl = (const float4*)(el + (size_t)loc[i] * 512);
    dst[t] = sl[t];                            // 512 floats = 128 float4
    if (t < 8) {
        const float4* st = (const float4*)(et + (size_t)tim[i] * 32);
        dst[128 + t] = st[t];                  // 32 floats = 8 float4
    }
}

// ---------------- bf16 tensor-core GEMM --------------------------------------
// C[M,N] = A[M,K] * (transB ? B[N,K]^T : B[K,N]) + bias
// blockIdx.x -> M tile, blockIdx.y -> N tile (consecutive CTAs share B tile)
#define GBM 128
#define GBN 128
#define GBK 32
#define GPAD 40

__global__ __launch_bounds__(256, 2)
void k_gemm(const float* __restrict__ A, const float* __restrict__ B,
            const float* __restrict__ bias, float* __restrict__ C,
            int M, int N, int K, int ldb, int ldc, int transB) {
    __shared__ __align__(16) __nv_bfloat16 As[GBM * GPAD];
    __shared__ __align__(16) __nv_bfloat16 Bs[GBN * GPAD];

    const int tid  = threadIdx.x;
    const int warp = tid >> 5, lane = tid & 31;
    const int wm = warp & 1;        // 2 warp-rows (M)
    const int wn = warp >> 1;       // 4 warp-cols (N)
    const int m0 = blockIdx.x * GBM;
    const int n0 = blockIdx.y * GBN;

    float acc[4][4][4];
#pragma unroll
    for (int i = 0; i < 4; i++)
#pragma unroll
        for (int j = 0; j < 4; j++)
#pragma unroll
            for (int r = 0; r < 4; r++) acc[i][j][r] = 0.f;

    const int lr = tid >> 3;        // 0..31
    const int lc = tid & 7;         // 0..7 (float4 within 32-wide k)

    for (int k0 = 0; k0 < K; k0 += GBK) {
#pragma unroll
        for (int i = 0; i < 4; i++) {
            int row = lr + 32 * i;
            float4 v = *(const float4*)(A + (size_t)(m0 + row) * K + k0 + 4 * lc);
            __nv_bfloat162* d = (__nv_bfloat162*)&As[row * GPAD + 4 * lc];
            d[0] = __floats2bfloat162_rn(v.x, v.y);
            d[1] = __floats2bfloat162_rn(v.z, v.w);
        }
        if (transB) {
#pragma unroll
            for (int i = 0; i < 4; i++) {
                int row = lr + 32 * i;
                int n = n0 + row;
                float4 v = make_float4(0.f, 0.f, 0.f, 0.f);
                if (n < N) v = *(const float4*)(B + (size_t)n * ldb + k0 + 4 * lc);
                __nv_bfloat162* d = (__nv_bfloat162*)&Bs[row * GPAD + 4 * lc];
                d[0] = __floats2bfloat162_rn(v.x, v.y);
                d[1] = __floats2bfloat162_rn(v.z, v.w);
            }
        } else {
            int kk = tid >> 3;
#pragma unroll
            for (int i = 0; i < 4; i++) {
                int n4 = lc + 8 * i;
                float4 v = *(const float4*)(B + (size_t)(k0 + kk) * ldb + n0 + 4 * n4);
                Bs[(4 * n4 + 0) * GPAD + kk] = __float2bfloat16(v.x);
                Bs[(4 * n4 + 1) * GPAD + kk] = __float2bfloat16(v.y);
                Bs[(4 * n4 + 2) * GPAD + kk] = __float2bfloat16(v.z);
                Bs[(4 * n4 + 3) * GPAD + kk] = __float2bfloat16(v.w);
            }
        }
        __syncthreads();

#pragma unroll
        for (int kk = 0; kk < 2; kk++) {
            uint32_t af[4][4], bf[4][2];
            const int r  = lane >> 2;
            const int cc = (lane & 3) * 2;
#pragma unroll
            for (int mt = 0; mt < 4; mt++) {
                int base = (wm * 64 + mt * 16 + r) * GPAD + kk * 16 + cc;
                af[mt][0] = *(const uint32_t*)&As[base];
                af[mt][1] = *(const uint32_t*)&As[base + 8 * GPAD];
                af[mt][2] = *(const uint32_t*)&As[base + 8];
                af[mt][3] = *(const uint32_t*)&As[base + 8 * GPAD + 8];
            }
#pragma unroll
            for (int nt = 0; nt < 4; nt++) {
                int col = wn * 32 + nt * 8 + r;
                int base = col * GPAD + kk * 16 + cc;
                bf[nt][0] = *(const uint32_t*)&Bs[base];
                bf[nt][1] = *(const uint32_t*)&Bs[base + 8];
            }
#pragma unroll
            for (int mt = 0; mt < 4; mt++)
#pragma unroll
                for (int nt = 0; nt < 4; nt++) {
                    asm volatile(
                        "mma.sync.aligned.m16n8k16.row.col.f32.bf16.bf16.f32 "
                        "{%0,%1,%2,%3}, {%4,%5,%6,%7}, {%8,%9}, {%0,%1,%2,%3};\n"
                        : "+f"(acc[mt][nt][0]), "+f"(acc[mt][nt][1]),
                          "+f"(acc[mt][nt][2]), "+f"(acc[mt][nt][3])
                        : "r"(af[mt][0]), "r"(af[mt][1]), "r"(af[mt][2]), "r"(af[mt][3]),
                          "r"(bf[nt][0]), "r"(bf[nt][1]));
                }
        }
        __syncthreads();
    }

    const int r  = lane >> 2;
    const int cc = (lane & 3) * 2;
#pragma unroll
    for (int mt = 0; mt < 4; mt++) {
        int row = m0 + wm * 64 + mt * 16 + r;
#pragma unroll
        for (int nt = 0; nt < 4; nt++) {
            int col = n0 + wn * 32 + nt * 8 + cc;
            if (col < N) {
                float b0 = bias ? bias[col] : 0.f;
                C[(size_t)row * ldc + col]       = acc[mt][nt][0] + b0;
                C[(size_t)(row + 8) * ldc + col] = acc[mt][nt][2] + b0;
            }
            if (col + 1 < N) {
                float b1 = bias ? bias[col + 1] : 0.f;
                C[(size_t)row * ldc + col + 1]       = acc[mt][nt][1] + b1;
                C[(size_t)(row + 8) * ldc + col + 1] = acc[mt][nt][3] + b1;
            }
        }
    }
}

// ---------------- persistent GRU ---------------------------------------------
// grid = 128 CTAs x 256 threads, 1 CTA/SM. Each warp owns one hidden unit.
// Whh slice lives in smem as bf16 (permuted for conflict-free uint4 loads).
// Cross-CTA sync is pure data polling: hbuf rows pre-poisoned to -inf; producers
// st.volatile their h value; consumers ld.volatile until all 4 lanes' words are
// finite. Self-synchronizing, no fence / atomic / counter.
__device__ __forceinline__ int wslot(int p) {   // p = even element index
    int m = p >> 8, r = p & 255;
    return (((m << 5) + ((r >> 2) & 31)) << 2) + ((r >> 7) << 1) + ((r >> 1) & 1);
}

__device__ __forceinline__ float dot8(uint4 w, float4 ha, float4 hb) {
    float s;
    s  = __uint_as_float(w.x << 16)          * ha.x;
    s += __uint_as_float(w.x & 0xFFFF0000u)  * ha.y;
    s += __uint_as_float(w.y << 16)          * ha.z;
    s += __uint_as_float(w.y & 0xFFFF0000u)  * ha.w;
    s += __uint_as_float(w.z << 16)          * hb.x;
    s += __uint_as_float(w.z & 0xFFFF0000u)  * hb.y;
    s += __uint_as_float(w.w << 16)          * hb.z;
    s += __uint_as_float(w.w & 0xFFFF0000u)  * hb.w;
    return s;
}

__global__ __launch_bounds__(256, 1)
void k_gru(const float* __restrict__ gi, const float* __restrict__ Whh,
           const float* __restrict__ bhh, float* __restrict__ hbuf, int steps) {
    extern __shared__ float sm[];
    uint32_t* wsm = (uint32_t*)sm;              // [8 warps][3 gates][512] bf16x2
    float* hsh = sm + 8 * 3 * 512;              // [2][1024] double buffer
    const int tid = threadIdx.x, warp = tid >> 5, lane = tid & 31;
    const int unit = blockIdx.x * 8 + warp;

    // stage this warp's 3 weight rows -> bf16, permuted layout
#pragma unroll
    for (int g = 0; g < 3; g++) {
        const float4* src = (const float4*)(Whh + (size_t)(g * HID + unit) * HID);
        uint32_t* dst = wsm + (warp * 3 + g) * 512;
        for (int i = lane; i < 256; i += 32) {
            float4 v = src[i];
            __nv_bfloat162 p0 = __floats2bfloat162_rn(v.x, v.y);
            __nv_bfloat162 p1 = __floats2bfloat162_rn(v.z, v.w);
            dst[wslot(4 * i)]     = *(uint32_t*)&p0;
            dst[wslot(4 * i + 2)] = *(uint32_t*)&p1;
        }
    }
    // no startup barrier needed: weights are warp-private; h row 0 was zeroed
    // by k_poison before this kernel launched.

    const float br = bhh[unit], bz = bhh[HID + unit], bn = bhh[2 * HID + unit];
    const uint4* w0q = (const uint4*)(wsm + warp * 3 * 512);
    const uint4* w1q = (const uint4*)(wsm + (warp * 3 + 1) * 512);
    const uint4* w2q = (const uint4*)(wsm + (warp * 3 + 2) * 512);

    int buf = 0;
    for (int t = 0; t < steps; t++) {
        // prefetch input gates (independent of h; in flight during the poll)
        float gir = 0.f, giz = 0.f, gin = 0.f;
        if (lane == 0) {
            const float* git = gi + (size_t)t * H3;
            gir = __ldg(git + unit);
            giz = __ldg(git + HID + unit);
            gin = __ldg(git + 2 * HID + unit);
        }
        // poll h(t): spin until all 4 words of this thread's float4 are finite
        const float* src = hbuf + (size_t)t * HID + 4 * tid;
        float4 hv;
        while (true) {
            asm volatile("ld.volatile.global.v4.f32 {%0,%1,%2,%3}, [%4];"
                         : "=f"(hv.x), "=f"(hv.y), "=f"(hv.z), "=f"(hv.w)
                         : "l"(src));
            if ((__float_as_uint(hv.x) != GINF) & (__float_as_uint(hv.y) != GINF) &
                (__float_as_uint(hv.z) != GINF) & (__float_as_uint(hv.w) != GINF))
                break;
        }
        float* hc = hsh + buf * HID;
        ((float4*)hc)[tid] = hv;
        __syncthreads();

        const float4* hq = (const float4*)hc;
        float s0 = 0.f, s1 = 0.f, s2 = 0.f;
#pragma unroll
        for (int m = 0; m < 4; m++) {
            float4 ha = hq[m * 64 + lane];
            float4 hb = hq[m * 64 + 32 + lane];
            s0 += dot8(w0q[m * 32 + lane], ha, hb);
            s1 += dot8(w1q[m * 32 + lane], ha, hb);
            s2 += dot8(w2q[m * 32 + lane], ha, hb);
        }
#pragma unroll
        for (int o = 16; o; o >>= 1) {
            s0 += __shfl_xor_sync(0xffffffffu, s0, o);
            s1 += __shfl_xor_sync(0xffffffffu, s1, o);
            s2 += __shfl_xor_sync(0xffffffffu, s2, o);
        }
        if (lane == 0) {
            float r = __fdividef(1.f, 1.f + __expf(-(gir + s0 + br)));
            float z = __fdividef(1.f, 1.f + __expf(-(giz + s1 + bz)));
            float xn = gin + r * (s2 + bn);
            float e2 = __expf(2.f * xn);
            float n = 1.f - __fdividef(2.f, e2 + 1.f);   // tanh(xn)
            float hn = (1.f - z) * n + z * hc[unit];
            asm volatile("st.volatile.global.f32 [%0], %1;" ::
                         "l"(hbuf + (size_t)(t + 1) * HID + unit), "f"(hn)
                         : "memory");
        }
        buf ^= 1;   // single sync/step: next write goes to the other buffer
    }
}

// ---------------- attention softmax (rows of 3072, in place) ------------------
__global__ void k_softmax_rows(float* __restrict__ e) {
    __shared__ float buf[SENC];
    __shared__ float red[256];
    const int row = blockIdx.x, tid = threadIdx.x;
    float* er = e + (size_t)row * SENC;

    float mx = -1e30f;
    for (int i = tid; i < SENC / 4; i += 256) {
        float4 v = ((const float4*)er)[i];
        ((float4*)buf)[i] = v;
        mx = fmaxf(mx, fmaxf(fmaxf(v.x, v.y), fmaxf(v.z, v.w)));
    }
    red[tid] = mx; __syncthreads();
    for (int s = 128; s; s >>= 1) { if (tid < s) red[tid] = fmaxf(red[tid], red[tid + s]); __syncthreads(); }
    mx = red[0]; __syncthreads();

    float sum = 0.f;
    for (int i = tid; i < SENC; i += 256) { float ev = __expf(buf[i] - mx); buf[i] = ev; sum += ev; }
    red[tid] = sum; __syncthreads();
    for (int s = 128; s; s >>= 1) { if (tid < s) red[tid] += red[tid + s]; __syncthreads(); }
    float inv = __fdividef(1.f, red[0]);

    for (int i = tid; i < SENC / 4; i += 256) {
        float4 v = ((const float4*)buf)[i];
        v.x *= inv; v.y *= inv; v.z *= inv; v.w *= inv;
        ((float4*)er)[i] = v;
    }
}

// ---------------- concat left half -------------------------------------------
__global__ void k_copy_h(const float* __restrict__ hs, float* __restrict__ cat) {
    int row = blockIdx.x;
    ((float4*)(cat + (size_t)row * 2 * HID))[threadIdx.x] =
        ((const float4*)(hs + (size_t)row * HID))[threadIdx.x];
}

// ---------------- fused log-softmax over 50000 (one pass, smem row) ----------
__global__ __launch_bounds__(256, 1)
void k_logsoftmax(float* __restrict__ y) {
    extern __shared__ float buf[];              // 50000 floats = 200 KB
    __shared__ float red[256];
    const int row = blockIdx.x, tid = threadIdx.x;
    float* yr = y + (size_t)row * VOC;

    float mx = -1e30f;
    for (int i = tid; i < VOC / 4; i += 256) {
        float4 v = ((const float4*)yr)[i];
        ((float4*)buf)[i] = v;
        mx = fmaxf(mx, fmaxf(fmaxf(v.x, v.y), fmaxf(v.z, v.w)));
    }
    red[tid] = mx; __syncthreads();
    for (int s = 128; s; s >>= 1) { if (tid < s) red[tid] = fmaxf(red[tid], red[tid + s]); __syncthreads(); }
    mx = red[0]; __syncthreads();

    float sum = 0.f;
    for (int i = tid; i < VOC; i += 256) sum += __expf(buf[i] - mx);
    red[tid] = sum; __syncthreads();
    for (int s = 128; s; s >>= 1) { if (tid < s) red[tid] += red[tid + s]; __syncthreads(); }
    const float lse = mx + logf(red[0]);

    for (int i = tid; i < VOC / 4; i += 256) {
        float4 v = ((const float4*)buf)[i];
        v.x -= lse; v.y -= lse; v.z -= lse; v.w -= lse;
        ((float4*)yr)[i] = v;
    }
}

// ---------------- launch ------------------------------------------------------
extern "C" void kernel_launch(void* const* d_in, const int* in_sizes, int n_in,
                              void* d_out, int out_size) {
    const int*   loc     = (const int*)d_in[0];
    const int*   tim     = (const int*)d_in[1];
    const float* emb_loc = (const float*)d_in[3];
    const float* emb_tim = (const float*)d_in[4];
    const float* Wih_e   = (const float*)d_in[5];
    const float* Whh_e   = (const float*)d_in[6];
    const float* bih_e   = (const float*)d_in[7];
    const float* bhh_e   = (const float*)d_in[8];
    const float* Wih_d   = (const float*)d_in[9];
    const float* Whh_d   = (const float*)d_in[10];
    const float* bih_d   = (const float*)d_in[11];
    const float* bhh_d   = (const float*)d_in[12];
    const float* W_fc    = (const float*)d_in[13];
    const float* b_fc    = (const float*)d_in[14];
    float* out = (float*)d_out;

    float *x, *gie, *gid, *he, *hd, *attn, *cat;
    cudaGetSymbolAddress((void**)&x,    g_x);
    cudaGetSymbolAddress((void**)&gie,  g_gi_enc);
    cudaGetSymbolAddress((void**)&gid,  g_gi_dec);
    cudaGetSymbolAddress((void**)&he,   g_henc);
    cudaGetSymbolAddress((void**)&hd,   g_hdec);
    cudaGetSymbolAddress((void**)&attn, g_attn);
    cudaGetSymbolAddress((void**)&cat,  g_cat);

    // 0. poison h buffers (row0=0, rest=-inf) — fresh every replay
    k_poison<<<512, 256>>>((uint4*)he, (SENC + 1) * HID / 4);
    k_poison<<<512, 256>>>((uint4*)hd, (TGT + 1) * HID / 4);

    // 1. embeddings
    k_embed<<<SEQ, 128>>>(loc, tim, emb_loc, emb_tim, x);

    // 2. input-gate GEMMs (gi = x @ Wih^T + bih)
    {
        dim3 g(SENC / GBM, H3 / GBN);
        k_gemm<<<g, 256>>>(x, Wih_e, bih_e, gie, SENC, H3, IN_DIM, IN_DIM, H3, 1);
    }
    {
        dim3 g(TGT / GBM, H3 / GBN);
        k_gemm<<<g, 256>>>(x + (size_t)SENC * IN_DIM, Wih_d, bih_d, gid, TGT, H3, IN_DIM, IN_DIM, H3, 1);
    }

    // 3. GRUs (persistent, bf16 smem weights, data-poll sync)
    size_t gsm = (size_t)(8 * 3 * 512) * 4 + 2 * HID * 4;   // 48KB + 8KB
    cudaFuncSetAttribute(k_gru, cudaFuncAttributeMaxDynamicSharedMemorySize, (int)gsm);
    k_gru<<<128, 256, gsm>>>(gie, Whh_e, bhh_e, he, SENC);
    k_gru<<<128, 256, gsm>>>(gid, Whh_d, bhh_d, hd, TGT);

    // 4. attention: energies = h_dec @ h_enc^T ; softmax ; context = attn @ h_enc
    {
        dim3 g(TGT / GBM, SENC / GBN);
        k_gemm<<<g, 256>>>(hd + HID, he + HID, nullptr, attn, TGT, SENC, HID, HID, SENC, 1);
    }
    k_softmax_rows<<<TGT, 256>>>(attn);
    {
        dim3 g(TGT / GBM, HID / GBN);
        k_gemm<<<g, 256>>>(attn, he + HID, nullptr, cat + HID, TGT, HID, SENC, HID, 2 * HID, 0);
    }
    k_copy_h<<<TGT, 256>>>(hd + HID, cat);

    // 5. FC + fused log-softmax
    {
        dim3 g(TGT / GBM, (VOC + GBN - 1) / GBN);
        k_gemm<<<g, 256>>>(cat, W_fc, b_fc, out, TGT, VOC, 2 * HID, 2 * HID, VOC, 1);
    }
    cudaFuncSetAttribute(k_logsoftmax, cudaFuncAttributeMaxDynamicSharedMemorySize, VOC * 4);
    k_logsoftmax<<<TGT, 256, VOC * 4>>>(out);
}